// round 11
// baseline (speedup 1.0000x reference)
#include <cuda_runtime.h>
#include <cuda_fp16.h>
#include <cstdint>

#define SEQ   2048
#define EMB   1024
#define NH    16
#define HD    64
#define BATCH 2
#define MROWS (BATCH*SEQ)   // 4096
#define NCOLS (3*EMB)       // 3072

// fp16 copies of the inputs (converted once per launch)
__device__ __half g_a[(size_t)MROWS * EMB];    // hidden, 8MB
__device__ __half g_w[(size_t)EMB * NCOLS];    // w_qkv, 6MB
// Head-split fp16 scratch: [b*NH+h][s][d]. Q pre-scaled by log2(e)/sqrt(EMB).
__device__ __half g_q[(size_t)BATCH * NH * SEQ * HD];
__device__ __half g_k[(size_t)BATCH * NH * SEQ * HD];
__device__ __half g_v[(size_t)BATCH * NH * SEQ * HD];

__device__ __forceinline__ uint32_t h2_u32(float a, float b) {
    __half2 h = __floats2half2_rn(a, b);
    return *(uint32_t*)&h;
}

__device__ __forceinline__ uint32_t ex2h2(uint32_t x) {
    uint32_t y;
    asm("ex2.approx.f16x2 %0, %1;" : "=r"(y) : "r"(x));
    return y;
}

// f32-accumulator fp16 MMA
__device__ __forceinline__ void mma_f16(float d[4],
                                        uint32_t a0, uint32_t a1, uint32_t a2, uint32_t a3,
                                        uint32_t b0, uint32_t b1) {
    asm volatile(
        "mma.sync.aligned.m16n8k16.row.col.f32.f16.f16.f32 "
        "{%0,%1,%2,%3}, {%4,%5,%6,%7}, {%8,%9}, {%0,%1,%2,%3};"
        : "+f"(d[0]), "+f"(d[1]), "+f"(d[2]), "+f"(d[3])
        : "r"(a0), "r"(a1), "r"(a2), "r"(a3), "r"(b0), "r"(b1));
}

// f16-accumulator fp16 MMA (packed D = A-frag layout of the next MMA)
__device__ __forceinline__ void mma_f16d(uint32_t d[2],
                                         uint32_t a0, uint32_t a1, uint32_t a2, uint32_t a3,
                                         uint32_t b0, uint32_t b1) {
    asm volatile(
        "mma.sync.aligned.m16n8k16.row.col.f16.f16.f16.f16 "
        "{%0,%1}, {%2,%3,%4,%5}, {%6,%7}, {%0,%1};"
        : "+r"(d[0]), "+r"(d[1])
        : "r"(a0), "r"(a1), "r"(a2), "r"(a3), "r"(b0), "r"(b1));
}

#define LDMX4(r0, r1, r2, r3, addr) \
    asm volatile("ldmatrix.sync.aligned.m8n8.x4.shared.b16 {%0,%1,%2,%3}, [%4];" \
                 : "=r"(r0), "=r"(r1), "=r"(r2), "=r"(r3) : "r"(addr))

#define LDMX4T(r0, r1, r2, r3, addr) \
    asm volatile("ldmatrix.sync.aligned.m8n8.x4.trans.shared.b16 {%0,%1,%2,%3}, [%4];" \
                 : "=r"(r0), "=r"(r1), "=r"(r2), "=r"(r3) : "r"(addr))

__device__ __forceinline__ void cp16(uint32_t dst, const void* src) {
    asm volatile("cp.async.cg.shared.global [%0], [%1], 16;"
                 :: "r"(dst), "l"(__cvta_generic_to_global(src)) : "memory");
}

__device__ __forceinline__ uint32_t smem_u32(const void* p) {
    uint32_t a;
    asm("{ .reg .u64 x; cvta.to.shared.u64 x, %1; cvt.u32.u64 %0, x; }" : "=r"(a) : "l"(p));
    return a;
}

// ---------------------------------------------------------------------------
// Kernel 0: fp32 -> fp16 conversion
// ---------------------------------------------------------------------------
__global__ __launch_bounds__(256) void cvt_f16(const float4* __restrict__ src,
                                               uint2* __restrict__ dst, int n4) {
    const int i = blockIdx.x * blockDim.x + threadIdx.x;
    if (i < n4) {
        float4 v = src[i];
        dst[i] = make_uint2(h2_u32(v.x, v.y), h2_u32(v.z, v.w));
    }
}

// ---------------------------------------------------------------------------
// Kernel 1: QKV GEMM, round-11: block 256x128, 512 threads = 16 warps of
// 64x32, ONE CTA per SM. A-tile amortized over 256 rows: L2 traffic drops
// 440 -> 334 MB. BK=64, cp.async double-buffered.
// ---------------------------------------------------------------------------
#define A_ROWB 144
#define B_ROWB 272
#define A_TILE (256 * A_ROWB)         // 36864
#define B_TILE (64 * B_ROWB)          // 17408
#define GSM_DYN (2 * (A_TILE + B_TILE))   // 108544
#define KITERS (EMB / 64)

__global__ __launch_bounds__(512, 1) void qkv_gemm() {
    extern __shared__ __align__(16) char smg[];
    const uint32_t smA = smem_u32(smg);
    const uint32_t smB = smA + 2 * A_TILE;

    const int t    = threadIdx.x;
    const int wid  = t >> 5;
    const int lane = t & 31;
    const int g    = lane >> 2;
    const int t4   = lane & 3;
    const int warpM = wid & 3;           // 0..3 -> 64 rows each (256 total)
    const int warpN = wid >> 2;          // 0..3 -> 32 cols each (128 total)
    const int rowBase = blockIdx.y * 256;
    const int colBase = blockIdx.x * 128;

    const __half* Ab = g_a + (size_t)rowBase * EMB;
    const __half* Wb = g_w + colBase;

    const uint32_t rowsel   = lane & 15;
    const uint32_t chunksel = (lane >> 4) * 16;
    const uint32_t aLM = smA + (warpM * 64 + rowsel) * A_ROWB + chunksel;
    const uint32_t bLM = smB + rowsel * B_ROWB + warpN * 64 + chunksel;

    // ---- stage k-tile 0: A 2048 chunks (4/thr), B 1024 chunks (2/thr) ----
    #pragma unroll
    for (int j = 0; j < 4; j++) {
        const int c = t + j * 512;
        cp16(smA + (c >> 3) * A_ROWB + (c & 7) * 16,
             Ab + (size_t)(c >> 3) * EMB + (c & 7) * 8);
    }
    #pragma unroll
    for (int j = 0; j < 2; j++) {
        const int c = t + j * 512;
        cp16(smB + (c >> 4) * B_ROWB + (c & 15) * 16,
             Wb + (size_t)(c >> 4) * NCOLS + (c & 15) * 8);
    }
    asm volatile("cp.async.commit_group;" ::: "memory");

    float acc[4][4][4] = {};

    for (int it = 0; it < KITERS; it++) {
        const int cur = it & 1;
        asm volatile("cp.async.wait_group 0;" ::: "memory");
        __syncthreads();

        if (it + 1 < KITERS) {
            const int k1 = (it + 1) * 64;
            const uint32_t dA = smA + (cur ^ 1) * A_TILE;
            const uint32_t dB = smB + (cur ^ 1) * B_TILE;
            #pragma unroll
            for (int j = 0; j < 4; j++) {
                const int c = t + j * 512;
                cp16(dA + (c >> 3) * A_ROWB + (c & 7) * 16,
                     Ab + (size_t)(c >> 3) * EMB + k1 + (c & 7) * 8);
            }
            #pragma unroll
            for (int j = 0; j < 2; j++) {
                const int c = t + j * 512;
                cp16(dB + (c >> 4) * B_ROWB + (c & 15) * 16,
                     Wb + (size_t)(k1 + (c >> 4)) * NCOLS + (c & 15) * 8);
            }
        }
        asm volatile("cp.async.commit_group;" ::: "memory");

        const uint32_t ka = aLM + cur * A_TILE;
        const uint32_t kb = bLM + cur * B_TILE;
        #pragma unroll
        for (int ks = 0; ks < 4; ks++) {
            uint32_t af[4][4];
            #pragma unroll
            for (int mt = 0; mt < 4; mt++)
                LDMX4(af[mt][0], af[mt][1], af[mt][2], af[mt][3],
                      ka + mt * 16 * A_ROWB + ks * 32);
            #pragma unroll
            for (int ntp = 0; ntp < 2; ntp++) {
                uint32_t b0, b1, b2, b3;
                LDMX4T(b0, b1, b2, b3, kb + ks * 16 * B_ROWB + ntp * 32);
                #pragma unroll
                for (int mt = 0; mt < 4; mt++) {
                    mma_f16(acc[mt][2 * ntp],     af[mt][0], af[mt][1], af[mt][2], af[mt][3], b0, b1);
                    mma_f16(acc[mt][2 * ntp + 1], af[mt][0], af[mt][1], af[mt][2], af[mt][3], b2, b3);
                }
            }
        }
    }

    // Epilogue: 128-col tile lies in one of Q/K/V; Q gets scale*log2e.
    const int part = colBase >> 10;
    __half* dst = (part == 0) ? g_q : (part == 1) ? g_k : g_v;
    const float sc = (part == 0) ? 0.03125f * 1.44269504f : 1.0f;

    #pragma unroll
    for (int mt = 0; mt < 4; mt++) {
        #pragma unroll
        for (int nt = 0; nt < 4; nt++) {
            const int c = colBase + warpN * 32 + nt * 8 + t4 * 2;
            const int e = c - part * EMB;
            const int h = e >> 6, d = e & 63;
            #pragma unroll
            for (int rr = 0; rr < 2; rr++) {
                const int m = rowBase + warpM * 64 + mt * 16 + g + rr * 8;
                const int b = m >> 11, s = m & 2047;
                const uint32_t hv = h2_u32(acc[mt][nt][rr * 2] * sc,
                                           acc[mt][nt][rr * 2 + 1] * sc);
                *(uint32_t*)(dst + (((size_t)(b * NH + h) * SEQ + s) * HD + d)) = hv;
            }
        }
    }
}

// ===========================================================================
// Kernel 2: flash attention (round-8 version restored — 95.3us, the best
// measured; round-10's 32-row warp tile regressed via occupancy collapse).
// ===========================================================================
#define NTILES  (SEQ / 64)
#define ROWB    144
#define TILE_B  (64 * ROWB)     // 9216
#define SM_DYN  (4 * TILE_B)    // 36864
#define ONES16  0x3C003C00u

__global__ __launch_bounds__(128, 5) void attn(float* __restrict__ out) {
    extern __shared__ __align__(16) char sh[];
    const uint32_t smb = smem_u32(sh);
    const uint32_t smK = smb;
    const uint32_t smV = smb + 2 * TILE_B;

    const int t    = threadIdx.x;
    const int wid  = t >> 5;
    const int lane = t & 31;
    const int g    = lane >> 2;
    const int t4   = lane & 3;
    const int bh   = blockIdx.y;
    const int q0   = blockIdx.x * 64;
    const int wrow = wid * 16;

    const __half* Qb = g_q + (size_t)bh * SEQ * HD;
    const __half* Kb = g_k + (size_t)bh * SEQ * HD;
    const __half* Vb = g_v + (size_t)bh * SEQ * HD;

    const uint32_t rowsel   = lane & 15;
    const uint32_t chunksel = (lane >> 4) * 16;
    const uint32_t kvLMoff = rowsel * ROWB + chunksel;

    // ---- stage Q through K-buffer-0, read fragments, then reuse buffer ----
    #pragma unroll
    for (int j = 0; j < 4; j++) {
        const int c = t + j * 128;
        const int row = c >> 3, c8 = c & 7;
        cp16(smK + row * ROWB + c8 * 16, Qb + (size_t)(q0 + row) * HD + c8 * 8);
    }
    asm volatile("cp.async.commit_group;" ::: "memory");
    asm volatile("cp.async.wait_group 0;" ::: "memory");
    __syncthreads();

    uint32_t qf[4][4];
    {
        const uint32_t qLM = smK + (wrow + rowsel) * ROWB + chunksel;
        #pragma unroll
        for (int ks = 0; ks < 4; ks++)
            LDMX4(qf[ks][0], qf[ks][1], qf[ks][2], qf[ks][3], qLM + ks * 32);
    }
    __syncthreads();

    // ---- stage K/V tile 0 ----
    #pragma unroll
    for (int j = 0; j < 4; j++) {
        const int c = t + j * 128;
        const int row = c >> 3, c8 = c & 7;
        cp16(smK + row * ROWB + c8 * 16, Kb + (size_t)row * HD + c8 * 8);
        cp16(smV + row * ROWB + c8 * 16, Vb + (size_t)row * HD + c8 * 8);
    }
    asm volatile("cp.async.commit_group;" ::: "memory");

    float O[8][4] = {};
    float Dl[4] = {};

    for (int tl = 0; tl < NTILES; tl++) {
        const int cur = tl & 1;
        asm volatile("cp.async.wait_group 0;" ::: "memory");
        __syncthreads();

        if (tl + 1 < NTILES) {
            const int k1 = (tl + 1) * 64;
            const uint32_t dK = smK + (cur ^ 1) * TILE_B;
            const uint32_t dV = smV + (cur ^ 1) * TILE_B;
            #pragma unroll
            for (int j = 0; j < 4; j++) {
                const int c = t + j * 128;
                const int row = c >> 3, c8 = c & 7;
                cp16(dK + row * ROWB + c8 * 16, Kb + (size_t)(k1 + row) * HD + c8 * 8);
                cp16(dV + row * ROWB + c8 * 16, Vb + (size_t)(k1 + row) * HD + c8 * 8);
            }
        }
        asm volatile("cp.async.commit_group;" ::: "memory");

        const uint32_t kb = smK + cur * TILE_B + kvLMoff;
        uint32_t sp[8][2];
        #pragma unroll
        for (int nt = 0; nt < 8; nt++) { sp[nt][0] = 0u; sp[nt][1] = 0u; }
        #pragma unroll
        for (int ks = 0; ks < 4; ks++) {
            #pragma unroll
            for (int np = 0; np < 4; np++) {
                uint32_t b0, b1, b2, b3;
                LDMX4(b0, b1, b2, b3, kb + np * 16 * ROWB + ks * 32);
                mma_f16d(sp[2 * np],     qf[ks][0], qf[ks][1], qf[ks][2], qf[ks][3], b0, b2);
                mma_f16d(sp[2 * np + 1], qf[ks][0], qf[ks][1], qf[ks][2], qf[ks][3], b1, b3);
            }
        }

        const uint32_t vb = smV + cur * TILE_B;
        #pragma unroll
        for (int ks = 0; ks < 4; ks++) {
            const uint32_t a0 = ex2h2(sp[2 * ks][0]);
            const uint32_t a1 = ex2h2(sp[2 * ks][1]);
            const uint32_t a2 = ex2h2(sp[2 * ks + 1][0]);
            const uint32_t a3 = ex2h2(sp[2 * ks + 1][1]);

            mma_f16(Dl, a0, a1, a2, a3, ONES16, ONES16);

            const uint32_t vk = vb + (ks * 16 + rowsel) * ROWB + chunksel;
            #pragma unroll
            for (int dp = 0; dp < 4; dp++) {
                uint32_t b0, b1, b2, b3;
                LDMX4T(b0, b1, b2, b3, vk + dp * 32);
                mma_f16(O[2 * dp],     a0, a1, a2, a3, b0, b1);
                mma_f16(O[2 * dp + 1], a0, a1, a2, a3, b2, b3);
            }
        }
    }

    const int b = bh >> 4, h = bh & 15;
    const float i0 = 1.0f / Dl[0], i1 = 1.0f / Dl[2];
    const int r0 = q0 + wrow + g;
    float* o0 = out + ((size_t)(b * SEQ + r0) * EMB) + h * HD + 2 * t4;
    float* o1 = out + ((size_t)(b * SEQ + r0 + 8) * EMB) + h * HD + 2 * t4;
    #pragma unroll
    for (int nt = 0; nt < 8; nt++) {
        *(float2*)(o0 + nt * 8) = make_float2(O[nt][0] * i0, O[nt][1] * i0);
        *(float2*)(o1 + nt * 8) = make_float2(O[nt][2] * i1, O[nt][3] * i1);
    }
}

// ---------------------------------------------------------------------------
extern "C" void kernel_launch(void* const* d_in, const int* in_sizes, int n_in,
                              void* d_out, int out_size) {
    const float* hidden = (const float*)d_in[0];  // [2,2048,1024] fp32
    const float* w_qkv  = (const float*)d_in[1];  // [1024,3072] fp32
    float* out = (float*)d_out;                   // [2,2048,1024] fp32

    static bool attr_set = false;
    if (!attr_set) {
        cudaFuncSetAttribute(qkv_gemm, cudaFuncAttributeMaxDynamicSharedMemorySize, GSM_DYN);
        cudaFuncSetAttribute(attn, cudaFuncAttributeMaxDynamicSharedMemorySize, SM_DYN);
        attr_set = true;
    }

    __half* da; cudaGetSymbolAddress((void**)&da, g_a);
    __half* dw; cudaGetSymbolAddress((void**)&dw, g_w);

    cvt_f16<<<(MROWS * EMB / 4 + 255) / 256, 256>>>((const float4*)hidden, (uint2*)da, MROWS * EMB / 4);
    cvt_f16<<<(EMB * NCOLS / 4 + 255) / 256, 256>>>((const float4*)w_qkv, (uint2*)dw, EMB * NCOLS / 4);
    qkv_gemm<<<dim3(NCOLS / 128, MROWS / 256), 512, GSM_DYN>>>();
    attn<<<dim3(SEQ / 64, BATCH * NH), 128, SM_DYN>>>(out);
}

// round 12
// speedup vs baseline: 1.0181x; 1.0181x over previous
#include <cuda_runtime.h>
#include <cuda_fp16.h>
#include <cstdint>

#define SEQ   2048
#define EMB   1024
#define NH    16
#define HD    64
#define BATCH 2
#define MROWS (BATCH*SEQ)   // 4096
#define NCOLS (3*EMB)       // 3072

// fp16 copies of the inputs (converted once per launch)
__device__ __half g_a[(size_t)MROWS * EMB];    // hidden, 8MB
__device__ __half g_w[(size_t)EMB * NCOLS];    // w_qkv, 6MB
// Head-split fp16 scratch: [b*NH+h][s][d]. Q pre-scaled by log2(e)/sqrt(EMB).
__device__ __half g_q[(size_t)BATCH * NH * SEQ * HD];
__device__ __half g_k[(size_t)BATCH * NH * SEQ * HD];
__device__ __half g_v[(size_t)BATCH * NH * SEQ * HD];

__device__ __forceinline__ uint32_t h2_u32(float a, float b) {
    __half2 h = __floats2half2_rn(a, b);
    return *(uint32_t*)&h;
}

__device__ __forceinline__ uint32_t ex2h2(uint32_t x) {
    uint32_t y;
    asm("ex2.approx.f16x2 %0, %1;" : "=r"(y) : "r"(x));
    return y;
}

// f32-accumulator fp16 MMA
__device__ __forceinline__ void mma_f16(float d[4],
                                        uint32_t a0, uint32_t a1, uint32_t a2, uint32_t a3,
                                        uint32_t b0, uint32_t b1) {
    asm volatile(
        "mma.sync.aligned.m16n8k16.row.col.f32.f16.f16.f32 "
        "{%0,%1,%2,%3}, {%4,%5,%6,%7}, {%8,%9}, {%0,%1,%2,%3};"
        : "+f"(d[0]), "+f"(d[1]), "+f"(d[2]), "+f"(d[3])
        : "r"(a0), "r"(a1), "r"(a2), "r"(a3), "r"(b0), "r"(b1));
}

// f16-accumulator fp16 MMA (packed D = A-frag layout of the next MMA)
__device__ __forceinline__ void mma_f16d(uint32_t d[2],
                                         uint32_t a0, uint32_t a1, uint32_t a2, uint32_t a3,
                                         uint32_t b0, uint32_t b1) {
    asm volatile(
        "mma.sync.aligned.m16n8k16.row.col.f16.f16.f16.f16 "
        "{%0,%1}, {%2,%3,%4,%5}, {%6,%7}, {%0,%1};"
        : "+r"(d[0]), "+r"(d[1])
        : "r"(a0), "r"(a1), "r"(a2), "r"(a3), "r"(b0), "r"(b1));
}

#define LDMX4(r0, r1, r2, r3, addr) \
    asm volatile("ldmatrix.sync.aligned.m8n8.x4.shared.b16 {%0,%1,%2,%3}, [%4];" \
                 : "=r"(r0), "=r"(r1), "=r"(r2), "=r"(r3) : "r"(addr))

#define LDMX4T(r0, r1, r2, r3, addr) \
    asm volatile("ldmatrix.sync.aligned.m8n8.x4.trans.shared.b16 {%0,%1,%2,%3}, [%4];" \
                 : "=r"(r0), "=r"(r1), "=r"(r2), "=r"(r3) : "r"(addr))

__device__ __forceinline__ void cp16(uint32_t dst, const void* src) {
    asm volatile("cp.async.cg.shared.global [%0], [%1], 16;"
                 :: "r"(dst), "l"(__cvta_generic_to_global(src)) : "memory");
}

__device__ __forceinline__ uint32_t smem_u32(const void* p) {
    uint32_t a;
    asm("{ .reg .u64 x; cvta.to.shared.u64 x, %1; cvt.u32.u64 %0, x; }" : "=r"(a) : "l"(p));
    return a;
}

// ---------------------------------------------------------------------------
// Kernel 0: fp32 -> fp16 conversion
// ---------------------------------------------------------------------------
__global__ __launch_bounds__(256) void cvt_f16(const float4* __restrict__ src,
                                               uint2* __restrict__ dst, int n4) {
    const int i = blockIdx.x * blockDim.x + threadIdx.x;
    if (i < n4) {
        float4 v = src[i];
        dst[i] = make_uint2(h2_u32(v.x, v.y), h2_u32(v.z, v.w));
    }
}

// ---------------------------------------------------------------------------
// Kernel 1: QKV GEMM (round-9 exact — best measured at ~85us).
// Block 128x128, 4 warps of 64x64, BK=64, cp.async double-buffered.
// ---------------------------------------------------------------------------
#define A_ROWB 144
#define B_ROWB 272
#define A_TILE (128 * A_ROWB)
#define B_TILE (64 * B_ROWB)
#define GSM_DYN (2 * A_TILE + 2 * B_TILE)   // 71680
#define KITERS (EMB / 64)

__global__ __launch_bounds__(128) void qkv_gemm() {
    extern __shared__ __align__(16) char smg[];
    const uint32_t smA = smem_u32(smg);
    const uint32_t smB = smA + 2 * A_TILE;

    const int t    = threadIdx.x;
    const int wid  = t >> 5;
    const int lane = t & 31;
    const int g    = lane >> 2;
    const int t4   = lane & 3;
    const int warpM = wid & 1;
    const int warpN = wid >> 1;
    const int rowBase = blockIdx.y * 128;
    const int colBase = blockIdx.x * 128;

    const __half* Ab = g_a + (size_t)rowBase * EMB;
    const __half* Wb = g_w + colBase;

    const uint32_t rowsel   = lane & 15;
    const uint32_t chunksel = (lane >> 4) * 16;
    const uint32_t aLM = smA + (warpM * 64 + rowsel) * A_ROWB + chunksel;
    const uint32_t bLM = smB + rowsel * B_ROWB + warpN * 128 + chunksel;

    #pragma unroll
    for (int j = 0; j < 8; j++) {
        const int c = t + j * 128;
        cp16(smA + (c >> 3) * A_ROWB + (c & 7) * 16,
             Ab + (size_t)(c >> 3) * EMB + (c & 7) * 8);
        cp16(smB + (c >> 4) * B_ROWB + (c & 15) * 16,
             Wb + (size_t)(c >> 4) * NCOLS + (c & 15) * 8);
    }
    asm volatile("cp.async.commit_group;" ::: "memory");

    float acc[4][8][4] = {};

    for (int it = 0; it < KITERS; it++) {
        const int cur = it & 1;
        asm volatile("cp.async.wait_group 0;" ::: "memory");
        __syncthreads();

        if (it + 1 < KITERS) {
            const int k1 = (it + 1) * 64;
            const uint32_t dA = smA + (cur ^ 1) * A_TILE;
            const uint32_t dB = smB + (cur ^ 1) * B_TILE;
            #pragma unroll
            for (int j = 0; j < 8; j++) {
                const int c = t + j * 128;
                cp16(dA + (c >> 3) * A_ROWB + (c & 7) * 16,
                     Ab + (size_t)(c >> 3) * EMB + k1 + (c & 7) * 8);
                cp16(dB + (c >> 4) * B_ROWB + (c & 15) * 16,
                     Wb + (size_t)(k1 + (c >> 4)) * NCOLS + (c & 15) * 8);
            }
        }
        asm volatile("cp.async.commit_group;" ::: "memory");

        const uint32_t ka = aLM + cur * A_TILE;
        const uint32_t kb = bLM + cur * B_TILE;
        #pragma unroll
        for (int ks = 0; ks < 4; ks++) {
            uint32_t af[4][4];
            #pragma unroll
            for (int mt = 0; mt < 4; mt++)
                LDMX4(af[mt][0], af[mt][1], af[mt][2], af[mt][3],
                      ka + mt * 16 * A_ROWB + ks * 32);
            #pragma unroll
            for (int dp = 0; dp < 4; dp++) {
                uint32_t b0, b1, b2, b3;
                LDMX4T(b0, b1, b2, b3, kb + ks * 16 * B_ROWB + dp * 32);
                #pragma unroll
                for (int mt = 0; mt < 4; mt++) {
                    mma_f16(acc[mt][2 * dp],     af[mt][0], af[mt][1], af[mt][2], af[mt][3], b0, b1);
                    mma_f16(acc[mt][2 * dp + 1], af[mt][0], af[mt][1], af[mt][2], af[mt][3], b2, b3);
                }
            }
        }
    }

    const int part = colBase >> 10;
    __half* dst = (part == 0) ? g_q : (part == 1) ? g_k : g_v;
    const float sc = (part == 0) ? 0.03125f * 1.44269504f : 1.0f;

    #pragma unroll
    for (int mt = 0; mt < 4; mt++) {
        #pragma unroll
        for (int nt = 0; nt < 8; nt++) {
            const int c = colBase + warpN * 64 + nt * 8 + t4 * 2;
            const int e = c - part * EMB;
            const int h = e >> 6, d = e & 63;
            #pragma unroll
            for (int rr = 0; rr < 2; rr++) {
                const int m = rowBase + warpM * 64 + mt * 16 + g + rr * 8;
                const int b = m >> 11, s = m & 2047;
                const uint32_t hv = h2_u32(acc[mt][nt][rr * 2] * sc,
                                           acc[mt][nt][rr * 2 + 1] * sc);
                *(uint32_t*)(dst + (((size_t)(b * NH + h) * SEQ + s) * HD + d)) = hv;
            }
        }
    }
}

// ===========================================================================
// Kernel 2: flash attention, round-12: padded 144B rows -> exact 128B rows
// with XOR swizzle (chunk ^= row&7). Smem 36.9 -> 32KB/CTA, targeting
// 5 CTAs/SM (round-11 profile showed a 4-CTA steady state). Structure
// otherwise identical to the proven round-8 kernel.
// ===========================================================================
#define NTILES  (SEQ / 64)
#define TILE_B  8192            // 64 rows * 128B, no padding
#define SM_DYN  (4 * TILE_B)    // 32768
#define ONES16  0x3C003C00u

// swizzled address of 16B chunk (row, ch) within a tile at byte base `tb`
__device__ __forceinline__ uint32_t swz(uint32_t tb, uint32_t row, uint32_t ch) {
    return tb + row * 128u + ((ch ^ (row & 7u)) << 4);
}

__global__ __launch_bounds__(128, 5) void attn(float* __restrict__ out) {
    extern __shared__ __align__(16) char sh[];
    const uint32_t smb = smem_u32(sh);
    const uint32_t smK = smb;                 // 2 buffers
    const uint32_t smV = smb + 2 * TILE_B;    // 2 buffers

    const int t    = threadIdx.x;
    const int wid  = t >> 5;
    const int lane = t & 31;
    const int g    = lane >> 2;
    const int t4   = lane & 3;
    const int bh   = blockIdx.y;
    const int q0   = blockIdx.x * 64;
    const int wrow = wid * 16;

    const __half* Qb = g_q + (size_t)bh * SEQ * HD;
    const __half* Kb = g_k + (size_t)bh * SEQ * HD;
    const __half* Vb = g_v + (size_t)bh * SEQ * HD;

    const uint32_t rowsel = lane & 15;          // ldmatrix row within 16
    const uint32_t cs     = lane >> 4;          // chunk lsb (0/1)
    const uint32_t m7     = rowsel & 7;         // swizzle mask for this lane

    // ---- stage Q (64 rows) through K-buffer-0, frags to regs, then reuse ----
    #pragma unroll
    for (int j = 0; j < 4; j++) {
        const int c = t + j * 128;
        const uint32_t row = c >> 3, c8 = c & 7;
        cp16(swz(smK, row, c8), Qb + (size_t)(q0 + row) * HD + c8 * 8);
    }
    asm volatile("cp.async.commit_group;" ::: "memory");
    asm volatile("cp.async.wait_group 0;" ::: "memory");
    __syncthreads();

    uint32_t qf[4][4];
    #pragma unroll
    for (int ks = 0; ks < 4; ks++)
        LDMX4(qf[ks][0], qf[ks][1], qf[ks][2], qf[ks][3],
              swz(smK, wrow + rowsel, 2 * ks + cs));
    __syncthreads();   // all warps done reading Q before K0 overwrites

    // ---- stage K/V tile 0 ----
    #pragma unroll
    for (int j = 0; j < 4; j++) {
        const int c = t + j * 128;
        const uint32_t row = c >> 3, c8 = c & 7;
        cp16(swz(smK, row, c8), Kb + (size_t)row * HD + c8 * 8);
        cp16(swz(smV, row, c8), Vb + (size_t)row * HD + c8 * 8);
    }
    asm volatile("cp.async.commit_group;" ::: "memory");

    float O[8][4] = {};
    float Dl[4] = {};

    for (int tl = 0; tl < NTILES; tl++) {
        const int cur = tl & 1;
        asm volatile("cp.async.wait_group 0;" ::: "memory");
        __syncthreads();

        if (tl + 1 < NTILES) {
            const int k1 = (tl + 1) * 64;
            const uint32_t dK = smK + (cur ^ 1) * TILE_B;
            const uint32_t dV = smV + (cur ^ 1) * TILE_B;
            #pragma unroll
            for (int j = 0; j < 4; j++) {
                const int c = t + j * 128;
                const uint32_t row = c >> 3, c8 = c & 7;
                cp16(swz(dK, row, c8), Kb + (size_t)(k1 + row) * HD + c8 * 8);
                cp16(swz(dV, row, c8), Vb + (size_t)(k1 + row) * HD + c8 * 8);
            }
        }
        asm volatile("cp.async.commit_group;" ::: "memory");

        // ---- S = Q K^T (f16 accum, packed) ----
        const uint32_t kb = smK + cur * TILE_B;
        uint32_t sp[8][2];
        #pragma unroll
        for (int nt = 0; nt < 8; nt++) { sp[nt][0] = 0u; sp[nt][1] = 0u; }
        #pragma unroll
        for (int ks = 0; ks < 4; ks++) {
            #pragma unroll
            for (int np = 0; np < 4; np++) {
                uint32_t b0, b1, b2, b3;
                LDMX4(b0, b1, b2, b3, swz(kb, np * 16 + rowsel, 2 * ks + cs));
                mma_f16d(sp[2 * np],     qf[ks][0], qf[ks][1], qf[ks][2], qf[ks][3], b0, b2);
                mma_f16d(sp[2 * np + 1], qf[ks][0], qf[ks][1], qf[ks][2], qf[ks][3], b1, b3);
            }
        }

        // ---- P = ex2(S); l += P·ones; O += P·V ----
        const uint32_t vb = smV + cur * TILE_B;
        #pragma unroll
        for (int ks = 0; ks < 4; ks++) {
            const uint32_t a0 = ex2h2(sp[2 * ks][0]);
            const uint32_t a1 = ex2h2(sp[2 * ks][1]);
            const uint32_t a2 = ex2h2(sp[2 * ks + 1][0]);
            const uint32_t a3 = ex2h2(sp[2 * ks + 1][1]);

            mma_f16(Dl, a0, a1, a2, a3, ONES16, ONES16);

            #pragma unroll
            for (int dp = 0; dp < 4; dp++) {
                uint32_t b0, b1, b2, b3;
                LDMX4T(b0, b1, b2, b3, swz(vb, ks * 16 + rowsel, 2 * dp + cs));
                mma_f16(O[2 * dp],     a0, a1, a2, a3, b0, b1);
                mma_f16(O[2 * dp + 1], a0, a1, a2, a3, b2, b3);
            }
        }
    }

    const int b = bh >> 4, h = bh & 15;
    const float i0 = 1.0f / Dl[0], i1 = 1.0f / Dl[2];
    const int r0 = q0 + wrow + g;
    float* o0 = out + ((size_t)(b * SEQ + r0) * EMB) + h * HD + 2 * t4;
    float* o1 = out + ((size_t)(b * SEQ + r0 + 8) * EMB) + h * HD + 2 * t4;
    #pragma unroll
    for (int nt = 0; nt < 8; nt++) {
        *(float2*)(o0 + nt * 8) = make_float2(O[nt][0] * i0, O[nt][1] * i0);
        *(float2*)(o1 + nt * 8) = make_float2(O[nt][2] * i1, O[nt][3] * i1);
    }
}

// ---------------------------------------------------------------------------
extern "C" void kernel_launch(void* const* d_in, const int* in_sizes, int n_in,
                              void* d_out, int out_size) {
    const float* hidden = (const float*)d_in[0];  // [2,2048,1024] fp32
    const float* w_qkv  = (const float*)d_in[1];  // [1024,3072] fp32
    float* out = (float*)d_out;                   // [2,2048,1024] fp32

    static bool attr_set = false;
    if (!attr_set) {
        cudaFuncSetAttribute(qkv_gemm, cudaFuncAttributeMaxDynamicSharedMemorySize, GSM_DYN);
        cudaFuncSetAttribute(attn, cudaFuncAttributeMaxDynamicSharedMemorySize, SM_DYN);
        attr_set = true;
    }

    __half* da; cudaGetSymbolAddress((void**)&da, g_a);
    __half* dw; cudaGetSymbolAddress((void**)&dw, g_w);

    cvt_f16<<<(MROWS * EMB / 4 + 255) / 256, 256>>>((const float4*)hidden, (uint2*)da, MROWS * EMB / 4);
    cvt_f16<<<(EMB * NCOLS / 4 + 255) / 256, 256>>>((const float4*)w_qkv, (uint2*)dw, EMB * NCOLS / 4);
    qkv_gemm<<<dim3(NCOLS / 128, MROWS / 128), 128, GSM_DYN>>>();
    attn<<<dim3(SEQ / 64, BATCH * NH), 128, SM_DYN>>>(out);
}

// round 14
// speedup vs baseline: 1.1038x; 1.0842x over previous
#include <cuda_runtime.h>
#include <cuda_fp16.h>
#include <cstdint>

#define SEQ   2048
#define EMB   1024
#define NH    16
#define HD    64
#define BATCH 2
#define MROWS (BATCH*SEQ)   // 4096
#define NCOLS (3*EMB)       // 3072

// fp16 copies of the inputs (converted once per launch)
__device__ __half g_a[(size_t)MROWS * EMB];    // hidden, 8MB
__device__ __half g_w[(size_t)EMB * NCOLS];    // w_qkv, 6MB
// Head-split fp16 scratch: [b*NH+h][s][d]. Q pre-scaled by log2(e)/sqrt(EMB).
__device__ __half g_q[(size_t)BATCH * NH * SEQ * HD];
__device__ __half g_k[(size_t)BATCH * NH * SEQ * HD];
__device__ __half g_v[(size_t)BATCH * NH * SEQ * HD];

__device__ __forceinline__ uint32_t h2_u32(float a, float b) {
    __half2 h = __floats2half2_rn(a, b);
    return *(uint32_t*)&h;
}

__device__ __forceinline__ uint32_t ex2h2(uint32_t x) {
    uint32_t y;
    asm("ex2.approx.f16x2 %0, %1;" : "=r"(y) : "r"(x));
    return y;
}

// f32-accumulator fp16 MMA
__device__ __forceinline__ void mma_f16(float d[4],
                                        uint32_t a0, uint32_t a1, uint32_t a2, uint32_t a3,
                                        uint32_t b0, uint32_t b1) {
    asm volatile(
        "mma.sync.aligned.m16n8k16.row.col.f32.f16.f16.f32 "
        "{%0,%1,%2,%3}, {%4,%5,%6,%7}, {%8,%9}, {%0,%1,%2,%3};"
        : "+f"(d[0]), "+f"(d[1]), "+f"(d[2]), "+f"(d[3])
        : "r"(a0), "r"(a1), "r"(a2), "r"(a3), "r"(b0), "r"(b1));
}

// f16-accumulator fp16 MMA (packed D = A-frag layout of the next MMA)
__device__ __forceinline__ void mma_f16d(uint32_t d[2],
                                         uint32_t a0, uint32_t a1, uint32_t a2, uint32_t a3,
                                         uint32_t b0, uint32_t b1) {
    asm volatile(
        "mma.sync.aligned.m16n8k16.row.col.f16.f16.f16.f16 "
        "{%0,%1}, {%2,%3,%4,%5}, {%6,%7}, {%0,%1};"
        : "+r"(d[0]), "+r"(d[1])
        : "r"(a0), "r"(a1), "r"(a2), "r"(a3), "r"(b0), "r"(b1));
}

#define LDMX4(r0, r1, r2, r3, addr) \
    asm volatile("ldmatrix.sync.aligned.m8n8.x4.shared.b16 {%0,%1,%2,%3}, [%4];" \
                 : "=r"(r0), "=r"(r1), "=r"(r2), "=r"(r3) : "r"(addr))

#define LDMX4T(r0, r1, r2, r3, addr) \
    asm volatile("ldmatrix.sync.aligned.m8n8.x4.trans.shared.b16 {%0,%1,%2,%3}, [%4];" \
                 : "=r"(r0), "=r"(r1), "=r"(r2), "=r"(r3) : "r"(addr))

__device__ __forceinline__ void cp16(uint32_t dst, const void* src) {
    asm volatile("cp.async.cg.shared.global [%0], [%1], 16;"
                 :: "r"(dst), "l"(__cvta_generic_to_global(src)) : "memory");
}

__device__ __forceinline__ uint32_t smem_u32(const void* p) {
    uint32_t a;
    asm("{ .reg .u64 x; cvta.to.shared.u64 x, %1; cvt.u32.u64 %0, x; }" : "=r"(a) : "l"(p));
    return a;
}

// swizzled chunk address: 128B rows (8 x 16B chunks)
__device__ __forceinline__ uint32_t swz(uint32_t tb, uint32_t row, uint32_t ch) {
    return tb + row * 128u + ((ch ^ (row & 7u)) << 4);
}
// swizzled chunk address: 256B rows (16 x 16B chunks; XOR low 3 bits only)
__device__ __forceinline__ uint32_t swzB(uint32_t tb, uint32_t row, uint32_t ch) {
    return tb + row * 256u + ((ch ^ (row & 7u)) << 4);
}

// ---------------------------------------------------------------------------
// Kernel 0: fp32 -> fp16 conversion of BOTH inputs in one launch
// ---------------------------------------------------------------------------
#define NA4 (MROWS * EMB / 4)       // 1048576
#define NW4 (EMB * NCOLS / 4)       //  786432

__global__ __launch_bounds__(256) void cvt_f16(const float4* __restrict__ srcA,
                                               const float4* __restrict__ srcW,
                                               uint2* __restrict__ dstA,
                                               uint2* __restrict__ dstW) {
    const int i = blockIdx.x * blockDim.x + threadIdx.x;
    if (i < NA4) {
        float4 v = srcA[i];
        dstA[i] = make_uint2(h2_u32(v.x, v.y), h2_u32(v.z, v.w));
    } else if (i < NA4 + NW4) {
        float4 v = srcW[i - NA4];
        dstW[i - NA4] = make_uint2(h2_u32(v.x, v.y), h2_u32(v.z, v.w));
    }
}

// ---------------------------------------------------------------------------
// Kernel 1: QKV GEMM: 256 thr = 8 warps of 64x32 + XOR-swizzled exact-size
// smem (64KB/CTA -> 2 CTAs/SM = 16 warps). Round-13 crash fix: B-fragment
// chunk offset is warpN*4 (32 cols = 64B = 4 chunks), NOT warpN*8.
// ---------------------------------------------------------------------------
#define GA_TILE 16384                 // 128 rows * 128B
#define GB_TILE 16384                 //  64 rows * 256B
#define GSM_DYN (2 * (GA_TILE + GB_TILE))   // 65536
#define KITERS (EMB / 64)

__global__ __launch_bounds__(256, 2) void qkv_gemm() {
    extern __shared__ __align__(16) char smg[];
    const uint32_t smA = smem_u32(smg);
    const uint32_t smB = smA + 2 * GA_TILE;

    const int t    = threadIdx.x;
    const int wid  = t >> 5;
    const int lane = t & 31;
    const int g    = lane >> 2;
    const int t4   = lane & 3;
    const int warpM = wid >> 2;          // 0..1 -> 64 rows
    const int warpN = wid & 3;           // 0..3 -> 32 cols
    const int rowBase = blockIdx.y * 128;
    const int colBase = blockIdx.x * 128;

    const __half* Ab = g_a + (size_t)rowBase * EMB;
    const __half* Wb = g_w + colBase;

    const uint32_t rowsel = lane & 15;
    const uint32_t cs     = lane >> 4;   // chunk lsb for ldmatrix

    // ---- stage k-tile 0: A 1024 chunks + B 1024 chunks, 4 each per thread ----
    #pragma unroll
    for (int j = 0; j < 4; j++) {
        const int c = t + j * 256;
        cp16(swz(smA, c >> 3, c & 7),
             Ab + (size_t)(c >> 3) * EMB + (c & 7) * 8);
        cp16(swzB(smB, c >> 4, c & 15),
             Wb + (size_t)(c >> 4) * NCOLS + (c & 15) * 8);
    }
    asm volatile("cp.async.commit_group;" ::: "memory");

    float acc[4][4][4] = {};

    for (int it = 0; it < KITERS; it++) {
        const int cur = it & 1;
        asm volatile("cp.async.wait_group 0;" ::: "memory");
        __syncthreads();

        if (it + 1 < KITERS) {
            const int k1 = (it + 1) * 64;
            const uint32_t dA = smA + (cur ^ 1) * GA_TILE;
            const uint32_t dB = smB + (cur ^ 1) * GB_TILE;
            #pragma unroll
            for (int j = 0; j < 4; j++) {
                const int c = t + j * 256;
                cp16(swz(dA, c >> 3, c & 7),
                     Ab + (size_t)(c >> 3) * EMB + k1 + (c & 7) * 8);
                cp16(swzB(dB, c >> 4, c & 15),
                     Wb + (size_t)(k1 + (c >> 4)) * NCOLS + (c & 15) * 8);
            }
        }
        asm volatile("cp.async.commit_group;" ::: "memory");

        const uint32_t ka = smA + cur * GA_TILE;
        const uint32_t kb = smB + cur * GB_TILE;
        #pragma unroll
        for (int ks = 0; ks < 4; ks++) {
            uint32_t af[4][4];
            #pragma unroll
            for (int mt = 0; mt < 4; mt++)
                LDMX4(af[mt][0], af[mt][1], af[mt][2], af[mt][3],
                      swz(ka, warpM * 64 + mt * 16 + rowsel, 2 * ks + cs));
            #pragma unroll
            for (int ntp = 0; ntp < 2; ntp++) {
                uint32_t q0, q1, q2, q3;
                LDMX4T(q0, q1, q2, q3,
                       swzB(kb, ks * 16 + rowsel, warpN * 4 + ntp * 2 + cs));
                #pragma unroll
                for (int mt = 0; mt < 4; mt++) {
                    mma_f16(acc[mt][2 * ntp],     af[mt][0], af[mt][1], af[mt][2], af[mt][3], q0, q1);
                    mma_f16(acc[mt][2 * ntp + 1], af[mt][0], af[mt][1], af[mt][2], af[mt][3], q2, q3);
                }
            }
        }
    }

    // Epilogue: 128-col tile lies in one of Q/K/V; Q gets scale*log2e.
    const int part = colBase >> 10;
    __half* dst = (part == 0) ? g_q : (part == 1) ? g_k : g_v;
    const float sc = (part == 0) ? 0.03125f * 1.44269504f : 1.0f;

    #pragma unroll
    for (int mt = 0; mt < 4; mt++) {
        #pragma unroll
        for (int nt = 0; nt < 4; nt++) {
            const int c = colBase + warpN * 32 + nt * 8 + t4 * 2;
            const int e = c - part * EMB;
            const int h = e >> 6, d = e & 63;
            #pragma unroll
            for (int rr = 0; rr < 2; rr++) {
                const int m = rowBase + warpM * 64 + mt * 16 + g + rr * 8;
                const int b = m >> 11, s = m & 2047;
                const uint32_t hv = h2_u32(acc[mt][nt][rr * 2] * sc,
                                           acc[mt][nt][rr * 2 + 1] * sc);
                *(uint32_t*)(dst + (((size_t)(b * NH + h) * SEQ + s) * HD + d)) = hv;
            }
        }
    }
}

// ===========================================================================
// Kernel 2: flash attention (round-12 exact — best measured, swizzled 32KB).
// ===========================================================================
#define NTILES  (SEQ / 64)
#define TILE_B  8192            // 64 rows * 128B, no padding
#define SM_DYN  (4 * TILE_B)    // 32768
#define ONES16  0x3C003C00u

__global__ __launch_bounds__(128, 5) void attn(float* __restrict__ out) {
    extern __shared__ __align__(16) char sh[];
    const uint32_t smb = smem_u32(sh);
    const uint32_t smK = smb;                 // 2 buffers
    const uint32_t smV = smb + 2 * TILE_B;    // 2 buffers

    const int t    = threadIdx.x;
    const int wid  = t >> 5;
    const int lane = t & 31;
    const int g    = lane >> 2;
    const int t4   = lane & 3;
    const int bh   = blockIdx.y;
    const int q0   = blockIdx.x * 64;
    const int wrow = wid * 16;

    const __half* Qb = g_q + (size_t)bh * SEQ * HD;
    const __half* Kb = g_k + (size_t)bh * SEQ * HD;
    const __half* Vb = g_v + (size_t)bh * SEQ * HD;

    const uint32_t rowsel = lane & 15;
    const uint32_t cs     = lane >> 4;

    // ---- stage Q (64 rows) through K-buffer-0, frags to regs, then reuse ----
    #pragma unroll
    for (int j = 0; j < 4; j++) {
        const int c = t + j * 128;
        const uint32_t row = c >> 3, c8 = c & 7;
        cp16(swz(smK, row, c8), Qb + (size_t)(q0 + row) * HD + c8 * 8);
    }
    asm volatile("cp.async.commit_group;" ::: "memory");
    asm volatile("cp.async.wait_group 0;" ::: "memory");
    __syncthreads();

    uint32_t qf[4][4];
    #pragma unroll
    for (int ks = 0; ks < 4; ks++)
        LDMX4(qf[ks][0], qf[ks][1], qf[ks][2], qf[ks][3],
              swz(smK, wrow + rowsel, 2 * ks + cs));
    __syncthreads();   // all warps done reading Q before K0 overwrites

    // ---- stage K/V tile 0 ----
    #pragma unroll
    for (int j = 0; j < 4; j++) {
        const int c = t + j * 128;
        const uint32_t row = c >> 3, c8 = c & 7;
        cp16(swz(smK, row, c8), Kb + (size_t)row * HD + c8 * 8);
        cp16(swz(smV, row, c8), Vb + (size_t)row * HD + c8 * 8);
    }
    asm volatile("cp.async.commit_group;" ::: "memory");

    float O[8][4] = {};
    float Dl[4] = {};

    for (int tl = 0; tl < NTILES; tl++) {
        const int cur = tl & 1;
        asm volatile("cp.async.wait_group 0;" ::: "memory");
        __syncthreads();

        if (tl + 1 < NTILES) {
            const int k1 = (tl + 1) * 64;
            const uint32_t dK = smK + (cur ^ 1) * TILE_B;
            const uint32_t dV = smV + (cur ^ 1) * TILE_B;
            #pragma unroll
            for (int j = 0; j < 4; j++) {
                const int c = t + j * 128;
                const uint32_t row = c >> 3, c8 = c & 7;
                cp16(swz(dK, row, c8), Kb + (size_t)(k1 + row) * HD + c8 * 8);
                cp16(swz(dV, row, c8), Vb + (size_t)(k1 + row) * HD + c8 * 8);
            }
        }
        asm volatile("cp.async.commit_group;" ::: "memory");

        // ---- S = Q K^T (f16 accum, packed) ----
        const uint32_t kb = smK + cur * TILE_B;
        uint32_t sp[8][2];
        #pragma unroll
        for (int nt = 0; nt < 8; nt++) { sp[nt][0] = 0u; sp[nt][1] = 0u; }
        #pragma unroll
        for (int ks = 0; ks < 4; ks++) {
            #pragma unroll
            for (int np = 0; np < 4; np++) {
                uint32_t b0, b1, b2, b3;
                LDMX4(b0, b1, b2, b3, swz(kb, np * 16 + rowsel, 2 * ks + cs));
                mma_f16d(sp[2 * np],     qf[ks][0], qf[ks][1], qf[ks][2], qf[ks][3], b0, b2);
                mma_f16d(sp[2 * np + 1], qf[ks][0], qf[ks][1], qf[ks][2], qf[ks][3], b1, b3);
            }
        }

        // ---- P = ex2(S); l += P·ones; O += P·V ----
        const uint32_t vb = smV + cur * TILE_B;
        #pragma unroll
        for (int ks = 0; ks < 4; ks++) {
            const uint32_t a0 = ex2h2(sp[2 * ks][0]);
            const uint32_t a1 = ex2h2(sp[2 * ks][1]);
            const uint32_t a2 = ex2h2(sp[2 * ks + 1][0]);
            const uint32_t a3 = ex2h2(sp[2 * ks + 1][1]);

            mma_f16(Dl, a0, a1, a2, a3, ONES16, ONES16);

            #pragma unroll
            for (int dp = 0; dp < 4; dp++) {
                uint32_t b0, b1, b2, b3;
                LDMX4T(b0, b1, b2, b3, swz(vb, ks * 16 + rowsel, 2 * dp + cs));
                mma_f16(O[2 * dp],     a0, a1, a2, a3, b0, b1);
                mma_f16(O[2 * dp + 1], a0, a1, a2, a3, b2, b3);
            }
        }
    }

    const int b = bh >> 4, h = bh & 15;
    const float i0 = 1.0f / Dl[0], i1 = 1.0f / Dl[2];
    const int r0 = q0 + wrow + g;
    float* o0 = out + ((size_t)(b * SEQ + r0) * EMB) + h * HD + 2 * t4;
    float* o1 = out + ((size_t)(b * SEQ + r0 + 8) * EMB) + h * HD + 2 * t4;
    #pragma unroll
    for (int nt = 0; nt < 8; nt++) {
        *(float2*)(o0 + nt * 8) = make_float2(O[nt][0] * i0, O[nt][1] * i0);
        *(float2*)(o1 + nt * 8) = make_float2(O[nt][2] * i1, O[nt][3] * i1);
    }
}

// ---------------------------------------------------------------------------
extern "C" void kernel_launch(void* const* d_in, const int* in_sizes, int n_in,
                              void* d_out, int out_size) {
    const float* hidden = (const float*)d_in[0];  // [2,2048,1024] fp32
    const float* w_qkv  = (const float*)d_in[1];  // [1024,3072] fp32
    float* out = (float*)d_out;                   // [2,2048,1024] fp32

    static bool attr_set = false;
    if (!attr_set) {
        cudaFuncSetAttribute(qkv_gemm, cudaFuncAttributeMaxDynamicSharedMemorySize, GSM_DYN);
        cudaFuncSetAttribute(attn, cudaFuncAttributeMaxDynamicSharedMemorySize, SM_DYN);
        cudaFuncSetAttribute(qkv_gemm, cudaFuncAttributePreferredSharedMemoryCarveout, 100);
        cudaFuncSetAttribute(attn, cudaFuncAttributePreferredSharedMemoryCarveout, 100);
        attr_set = true;
    }

    __half* da; cudaGetSymbolAddress((void**)&da, g_a);
    __half* dw; cudaGetSymbolAddress((void**)&dw, g_w);

    cvt_f16<<<(NA4 + NW4 + 255) / 256, 256>>>((const float4*)hidden, (const float4*)w_qkv,
                                              (uint2*)da, (uint2*)dw);
    qkv_gemm<<<dim3(NCOLS / 128, MROWS / 128), 256, GSM_DYN>>>();
    attn<<<dim3(SEQ / 64, BATCH * NH), 128, SM_DYN>>>(out);
}

// round 15
// speedup vs baseline: 1.1558x; 1.0471x over previous
#include <cuda_runtime.h>
#include <cuda_fp16.h>
#include <cstdint>

#define SEQ   2048
#define EMB   1024
#define NH    16
#define HD    64
#define BATCH 2
#define MROWS (BATCH*SEQ)   // 4096
#define NCOLS (3*EMB)       // 3072

// fp16 copies of the inputs (converted once per launch)
__device__ __half g_a[(size_t)MROWS * EMB];    // hidden, 8MB
__device__ __half g_w[(size_t)EMB * NCOLS];    // w_qkv, 6MB
// Head-split fp16 scratch: [b*NH+h][s][d]. Q pre-scaled by log2(e)/sqrt(EMB).
__device__ __half g_q[(size_t)BATCH * NH * SEQ * HD];
__device__ __half g_k[(size_t)BATCH * NH * SEQ * HD];
__device__ __half g_v[(size_t)BATCH * NH * SEQ * HD];

__device__ __forceinline__ uint32_t h2_u32(float a, float b) {
    __half2 h = __floats2half2_rn(a, b);
    return *(uint32_t*)&h;
}

__device__ __forceinline__ uint32_t ex2h2(uint32_t x) {
    uint32_t y;
    asm("ex2.approx.f16x2 %0, %1;" : "=r"(y) : "r"(x));
    return y;
}

// f32-accumulator fp16 MMA
__device__ __forceinline__ void mma_f16(float d[4],
                                        uint32_t a0, uint32_t a1, uint32_t a2, uint32_t a3,
                                        uint32_t b0, uint32_t b1) {
    asm volatile(
        "mma.sync.aligned.m16n8k16.row.col.f32.f16.f16.f32 "
        "{%0,%1,%2,%3}, {%4,%5,%6,%7}, {%8,%9}, {%0,%1,%2,%3};"
        : "+f"(d[0]), "+f"(d[1]), "+f"(d[2]), "+f"(d[3])
        : "r"(a0), "r"(a1), "r"(a2), "r"(a3), "r"(b0), "r"(b1));
}

// f16-accumulator fp16 MMA (packed D = A-frag layout of the next MMA)
__device__ __forceinline__ void mma_f16d(uint32_t d[2],
                                         uint32_t a0, uint32_t a1, uint32_t a2, uint32_t a3,
                                         uint32_t b0, uint32_t b1) {
    asm volatile(
        "mma.sync.aligned.m16n8k16.row.col.f16.f16.f16.f16 "
        "{%0,%1}, {%2,%3,%4,%5}, {%6,%7}, {%0,%1};"
        : "+r"(d[0]), "+r"(d[1])
        : "r"(a0), "r"(a1), "r"(a2), "r"(a3), "r"(b0), "r"(b1));
}

#define LDMX4(r0, r1, r2, r3, addr) \
    asm volatile("ldmatrix.sync.aligned.m8n8.x4.shared.b16 {%0,%1,%2,%3}, [%4];" \
                 : "=r"(r0), "=r"(r1), "=r"(r2), "=r"(r3) : "r"(addr))

#define LDMX4T(r0, r1, r2, r3, addr) \
    asm volatile("ldmatrix.sync.aligned.m8n8.x4.trans.shared.b16 {%0,%1,%2,%3}, [%4];" \
                 : "=r"(r0), "=r"(r1), "=r"(r2), "=r"(r3) : "r"(addr))

__device__ __forceinline__ void cp16(uint32_t dst, const void* src) {
    asm volatile("cp.async.cg.shared.global [%0], [%1], 16;"
                 :: "r"(dst), "l"(__cvta_generic_to_global(src)) : "memory");
}

__device__ __forceinline__ uint32_t smem_u32(const void* p) {
    uint32_t a;
    asm("{ .reg .u64 x; cvta.to.shared.u64 x, %1; cvt.u32.u64 %0, x; }" : "=r"(a) : "l"(p));
    return a;
}

// swizzled chunk address: 128B rows (8 x 16B chunks)
__device__ __forceinline__ uint32_t swz(uint32_t tb, uint32_t row, uint32_t ch) {
    return tb + row * 128u + ((ch ^ (row & 7u)) << 4);
}
// swizzled chunk address: 256B rows (16 x 16B chunks; XOR low 3 bits only)
__device__ __forceinline__ uint32_t swzB(uint32_t tb, uint32_t row, uint32_t ch) {
    return tb + row * 256u + ((ch ^ (row & 7u)) << 4);
}

// ---------------------------------------------------------------------------
// Kernel 0: fp32 -> fp16 conversion, MLP=4 (was latency-bound at MLP=1).
// Each 256-thread block converts 1024 float4 chunks; NA4 and NW4 are both
// divisible by 1024, so every block lies entirely in one region.
// ---------------------------------------------------------------------------
#define NA4 (MROWS * EMB / 4)       // 1048576
#define NW4 (EMB * NCOLS / 4)       //  786432

__global__ __launch_bounds__(256) void cvt_f16(const float4* __restrict__ srcA,
                                               const float4* __restrict__ srcW,
                                               uint2* __restrict__ dstA,
                                               uint2* __restrict__ dstW) {
    int base = blockIdx.x * 1024 + threadIdx.x;
    const float4* src = srcA;
    uint2* dst = dstA;
    if (base >= NA4) { base -= NA4; src = srcW; dst = dstW; }
    float4 v0 = src[base];
    float4 v1 = src[base + 256];
    float4 v2 = src[base + 512];
    float4 v3 = src[base + 768];
    dst[base]       = make_uint2(h2_u32(v0.x, v0.y), h2_u32(v0.z, v0.w));
    dst[base + 256] = make_uint2(h2_u32(v1.x, v1.y), h2_u32(v1.z, v1.w));
    dst[base + 512] = make_uint2(h2_u32(v2.x, v2.y), h2_u32(v2.z, v2.w));
    dst[base + 768] = make_uint2(h2_u32(v3.x, v3.y), h2_u32(v3.z, v3.w));
}

// ---------------------------------------------------------------------------
// Kernel 1: QKV GEMM (round-14 exact — 16 warps/SM, ~70us proven).
// ---------------------------------------------------------------------------
#define GA_TILE 16384                 // 128 rows * 128B
#define GB_TILE 16384                 //  64 rows * 256B
#define GSM_DYN (2 * (GA_TILE + GB_TILE))   // 65536
#define KITERS (EMB / 64)

__global__ __launch_bounds__(256, 2) void qkv_gemm() {
    extern __shared__ __align__(16) char smg[];
    const uint32_t smA = smem_u32(smg);
    const uint32_t smB = smA + 2 * GA_TILE;

    const int t    = threadIdx.x;
    const int wid  = t >> 5;
    const int lane = t & 31;
    const int g    = lane >> 2;
    const int t4   = lane & 3;
    const int warpM = wid >> 2;
    const int warpN = wid & 3;
    const int rowBase = blockIdx.y * 128;
    const int colBase = blockIdx.x * 128;

    const __half* Ab = g_a + (size_t)rowBase * EMB;
    const __half* Wb = g_w + colBase;

    const uint32_t rowsel = lane & 15;
    const uint32_t cs     = lane >> 4;

    #pragma unroll
    for (int j = 0; j < 4; j++) {
        const int c = t + j * 256;
        cp16(swz(smA, c >> 3, c & 7),
             Ab + (size_t)(c >> 3) * EMB + (c & 7) * 8);
        cp16(swzB(smB, c >> 4, c & 15),
             Wb + (size_t)(c >> 4) * NCOLS + (c & 15) * 8);
    }
    asm volatile("cp.async.commit_group;" ::: "memory");

    float acc[4][4][4] = {};

    for (int it = 0; it < KITERS; it++) {
        const int cur = it & 1;
        asm volatile("cp.async.wait_group 0;" ::: "memory");
        __syncthreads();

        if (it + 1 < KITERS) {
            const int k1 = (it + 1) * 64;
            const uint32_t dA = smA + (cur ^ 1) * GA_TILE;
            const uint32_t dB = smB + (cur ^ 1) * GB_TILE;
            #pragma unroll
            for (int j = 0; j < 4; j++) {
                const int c = t + j * 256;
                cp16(swz(dA, c >> 3, c & 7),
                     Ab + (size_t)(c >> 3) * EMB + k1 + (c & 7) * 8);
                cp16(swzB(dB, c >> 4, c & 15),
                     Wb + (size_t)(k1 + (c >> 4)) * NCOLS + (c & 15) * 8);
            }
        }
        asm volatile("cp.async.commit_group;" ::: "memory");

        const uint32_t ka = smA + cur * GA_TILE;
        const uint32_t kb = smB + cur * GB_TILE;
        #pragma unroll
        for (int ks = 0; ks < 4; ks++) {
            uint32_t af[4][4];
            #pragma unroll
            for (int mt = 0; mt < 4; mt++)
                LDMX4(af[mt][0], af[mt][1], af[mt][2], af[mt][3],
                      swz(ka, warpM * 64 + mt * 16 + rowsel, 2 * ks + cs));
            #pragma unroll
            for (int ntp = 0; ntp < 2; ntp++) {
                uint32_t q0, q1, q2, q3;
                LDMX4T(q0, q1, q2, q3,
                       swzB(kb, ks * 16 + rowsel, warpN * 4 + ntp * 2 + cs));
                #pragma unroll
                for (int mt = 0; mt < 4; mt++) {
                    mma_f16(acc[mt][2 * ntp],     af[mt][0], af[mt][1], af[mt][2], af[mt][3], q0, q1);
                    mma_f16(acc[mt][2 * ntp + 1], af[mt][0], af[mt][1], af[mt][2], af[mt][3], q2, q3);
                }
            }
        }
    }

    const int part = colBase >> 10;
    __half* dst = (part == 0) ? g_q : (part == 1) ? g_k : g_v;
    const float sc = (part == 0) ? 0.03125f * 1.44269504f : 1.0f;

    #pragma unroll
    for (int mt = 0; mt < 4; mt++) {
        #pragma unroll
        for (int nt = 0; nt < 4; nt++) {
            const int c = colBase + warpN * 32 + nt * 8 + t4 * 2;
            const int e = c - part * EMB;
            const int h = e >> 6, d = e & 63;
            #pragma unroll
            for (int rr = 0; rr < 2; rr++) {
                const int m = rowBase + warpM * 64 + mt * 16 + g + rr * 8;
                const int b = m >> 11, s = m & 2047;
                const uint32_t hv = h2_u32(acc[mt][nt][rr * 2] * sc,
                                           acc[mt][nt][rr * 2 + 1] * sc);
                *(uint32_t*)(dst + (((size_t)(b * NH + h) * SEQ + s) * HD + d)) = hv;
            }
        }
    }
}

// ===========================================================================
// Kernel 2: flash attention, round-15: BK 64 -> 32. Smem 32 -> 16KB/CTA,
// regs cap at 5 CTAs/SM = 20 warps (was 16). LDSM:MMA ratio identical —
// pure occupancy experiment on the 63%-tensor plateau.
// ===========================================================================
#define NTILES  (SEQ / 32)      // 64
#define TILE_B  4096            // 32 rows * 128B
#define SM_DYN  (4 * TILE_B)    // 16384
#define ONES16  0x3C003C00u

__global__ __launch_bounds__(128, 5) void attn(float* __restrict__ out) {
    extern __shared__ __align__(16) char sh[];
    const uint32_t smb = smem_u32(sh);
    const uint32_t smK = smb;                 // 2 buffers (4KB each)
    const uint32_t smV = smb + 2 * TILE_B;    // 2 buffers

    const int t    = threadIdx.x;
    const int wid  = t >> 5;
    const int lane = t & 31;
    const int g    = lane >> 2;
    const int t4   = lane & 3;
    const int bh   = blockIdx.y;
    const int q0   = blockIdx.x * 64;
    const int wrow = wid * 16;

    const __half* Qb = g_q + (size_t)bh * SEQ * HD;
    const __half* Kb = g_k + (size_t)bh * SEQ * HD;
    const __half* Vb = g_v + (size_t)bh * SEQ * HD;

    const uint32_t rowsel = lane & 15;
    const uint32_t cs     = lane >> 4;

    // ---- stage 64 Q rows across BOTH K buffers (2*4KB = exactly 64 rows) ----
    #pragma unroll
    for (int j = 0; j < 4; j++) {
        const int c = t + j * 128;
        const uint32_t row = c >> 3, c8 = c & 7;
        cp16(swz(smK, row, c8), Qb + (size_t)(q0 + row) * HD + c8 * 8);
    }
    asm volatile("cp.async.commit_group;" ::: "memory");
    asm volatile("cp.async.wait_group 0;" ::: "memory");
    __syncthreads();

    uint32_t qf[4][4];
    #pragma unroll
    for (int ks = 0; ks < 4; ks++)
        LDMX4(qf[ks][0], qf[ks][1], qf[ks][2], qf[ks][3],
              swz(smK, wrow + rowsel, 2 * ks + cs));
    __syncthreads();   // all warps done reading Q before K0 overwrites

    // ---- stage K/V tile 0 (32 rows each) ----
    #pragma unroll
    for (int j = 0; j < 2; j++) {
        const int c = t + j * 128;
        const uint32_t row = c >> 3, c8 = c & 7;
        cp16(swz(smK, row, c8), Kb + (size_t)row * HD + c8 * 8);
        cp16(swz(smV, row, c8), Vb + (size_t)row * HD + c8 * 8);
    }
    asm volatile("cp.async.commit_group;" ::: "memory");

    float O[8][4] = {};
    float Dl[4] = {};

    for (int tl = 0; tl < NTILES; tl++) {
        const int cur = tl & 1;
        asm volatile("cp.async.wait_group 0;" ::: "memory");
        __syncthreads();

        if (tl + 1 < NTILES) {
            const int k1 = (tl + 1) * 32;
            const uint32_t dK = smK + (cur ^ 1) * TILE_B;
            const uint32_t dV = smV + (cur ^ 1) * TILE_B;
            #pragma unroll
            for (int j = 0; j < 2; j++) {
                const int c = t + j * 128;
                const uint32_t row = c >> 3, c8 = c & 7;
                cp16(swz(dK, row, c8), Kb + (size_t)(k1 + row) * HD + c8 * 8);
                cp16(swz(dV, row, c8), Vb + (size_t)(k1 + row) * HD + c8 * 8);
            }
        }
        asm volatile("cp.async.commit_group;" ::: "memory");

        // ---- S = Q K^T over 32 keys (2 n-groups of 16) ----
        const uint32_t kb = smK + cur * TILE_B;
        uint32_t sp[4][2];
        #pragma unroll
        for (int nt = 0; nt < 4; nt++) { sp[nt][0] = 0u; sp[nt][1] = 0u; }
        #pragma unroll
        for (int ks = 0; ks < 4; ks++) {
            #pragma unroll
            for (int np = 0; np < 2; np++) {
                uint32_t b0, b1, b2, b3;
                LDMX4(b0, b1, b2, b3, swz(kb, np * 16 + rowsel, 2 * ks + cs));
                mma_f16d(sp[2 * np],     qf[ks][0], qf[ks][1], qf[ks][2], qf[ks][3], b0, b2);
                mma_f16d(sp[2 * np + 1], qf[ks][0], qf[ks][1], qf[ks][2], qf[ks][3], b1, b3);
            }
        }

        // ---- P = ex2(S); l += P·ones; O += P·V (2 k16-steps) ----
        const uint32_t vb = smV + cur * TILE_B;
        #pragma unroll
        for (int ks = 0; ks < 2; ks++) {
            const uint32_t a0 = ex2h2(sp[2 * ks][0]);
            const uint32_t a1 = ex2h2(sp[2 * ks][1]);
            const uint32_t a2 = ex2h2(sp[2 * ks + 1][0]);
            const uint32_t a3 = ex2h2(sp[2 * ks + 1][1]);

            mma_f16(Dl, a0, a1, a2, a3, ONES16, ONES16);

            #pragma unroll
            for (int dp = 0; dp < 4; dp++) {
                uint32_t b0, b1, b2, b3;
                LDMX4T(b0, b1, b2, b3, swz(vb, ks * 16 + rowsel, 2 * dp + cs));
                mma_f16(O[2 * dp],     a0, a1, a2, a3, b0, b1);
                mma_f16(O[2 * dp + 1], a0, a1, a2, a3, b2, b3);
            }
        }
    }

    const int b = bh >> 4, h = bh & 15;
    const float i0 = 1.0f / Dl[0], i1 = 1.0f / Dl[2];
    const int r0 = q0 + wrow + g;
    float* o0 = out + ((size_t)(b * SEQ + r0) * EMB) + h * HD + 2 * t4;
    float* o1 = out + ((size_t)(b * SEQ + r0 + 8) * EMB) + h * HD + 2 * t4;
    #pragma unroll
    for (int nt = 0; nt < 8; nt++) {
        *(float2*)(o0 + nt * 8) = make_float2(O[nt][0] * i0, O[nt][1] * i0);
        *(float2*)(o1 + nt * 8) = make_float2(O[nt][2] * i1, O[nt][3] * i1);
    }
}

// ---------------------------------------------------------------------------
extern "C" void kernel_launch(void* const* d_in, const int* in_sizes, int n_in,
                              void* d_out, int out_size) {
    const float* hidden = (const float*)d_in[0];  // [2,2048,1024] fp32
    const float* w_qkv  = (const float*)d_in[1];  // [1024,3072] fp32
    float* out = (float*)d_out;                   // [2,2048,1024] fp32

    static bool attr_set = false;
    if (!attr_set) {
        cudaFuncSetAttribute(qkv_gemm, cudaFuncAttributeMaxDynamicSharedMemorySize, GSM_DYN);
        cudaFuncSetAttribute(attn, cudaFuncAttributeMaxDynamicSharedMemorySize, SM_DYN);
        cudaFuncSetAttribute(qkv_gemm, cudaFuncAttributePreferredSharedMemoryCarveout, 100);
        cudaFuncSetAttribute(attn, cudaFuncAttributePreferredSharedMemoryCarveout, 100);
        attr_set = true;
    }

    __half* da; cudaGetSymbolAddress((void**)&da, g_a);
    __half* dw; cudaGetSymbolAddress((void**)&dw, g_w);

    cvt_f16<<<(NA4 + NW4) / 1024, 256>>>((const float4*)hidden, (const float4*)w_qkv,
                                         (uint2*)da, (uint2*)dw);
    qkv_gemm<<<dim3(NCOLS / 128, MROWS / 128), 256, GSM_DYN>>>();
    attn<<<dim3(SEQ / 64, BATCH * NH), 128, SM_DYN>>>(out);
}